// round 12
// baseline (speedup 1.0000x reference)
#include <cuda_runtime.h>

#define C_CH 32
#define HW   256
#define KS2  9
#define OCH  288
#define QS   32
#define NB   4

#define FSTR 264   // fmt row stride (words); interior cols 4..259 (16B aligned)

__device__ float g_p[NB * C_CH * QS * QS];   // [n][c][32][32]
__device__ float g_y[NB * OCH * QS * QS];    // [n][o][32][32]

// ---- f32x2 packed helpers (sm_103a native) ----
typedef unsigned long long u64;
__device__ __forceinline__ u64 pk2(float lo, float hi) {
    u64 r; asm("mov.b64 %0, {%1, %2};" : "=l"(r) : "f"(lo), "f"(hi)); return r;
}
__device__ __forceinline__ float2 unpk2(u64 v) {
    float2 f; asm("mov.b64 {%0, %1}, %2;" : "=f"(f.x), "=f"(f.y) : "l"(v)); return f;
}
__device__ __forceinline__ u64 ffma2(u64 a, u64 b, u64 c) {
    u64 d; asm("fma.rn.f32x2 %0, %1, %2, %3;" : "=l"(d) : "l"(a), "l"(b), "l"(c)); return d;
}
__device__ __forceinline__ u64 fadd2(u64 a, u64 b) {
    u64 d; asm("add.rn.f32x2 %0, %1, %2;" : "=l"(d) : "l"(a), "l"(b)); return d;
}
__device__ __forceinline__ u64 fneg2(u64 a) { return a ^ 0x8000000080000000ULL; }

// ---------------------------------------------------------------------------
// Kernel A: psf -> bilinear 1/4 -> maxpool2 -> g_p  (unchanged)
// ---------------------------------------------------------------------------
__global__ void __launch_bounds__(256) kA(const float* __restrict__ psf) {
    const int b  = blockIdx.x;
    const int it = b & 7;
    const int c  = (b >> 3) & 31;
    const int n  = b >> 8;
    const int tid  = threadIdx.x;
    const int warp = tid >> 5;
    const int lane = tid & 31;
    const int ii   = warp >> 1;
    const int half = warp & 1;
    const int i = it * 4 + ii;

    const float4* base = (const float4*)(psf + ((size_t)(n * C_CH + c) * HW) * HW);
    const int r0 = 8 * i + 1 + 4 * half;
    const float4* p0 = base + r0 * (HW / 4);
    const float4* p1 = p0 + (HW / 4);

    float4 a0 = __ldg(p0 + lane);
    float4 a1 = __ldg(p0 + 32 + lane);
    float4 b0 = __ldg(p1 + lane);
    float4 b1 = __ldg(p1 + 32 + lane);

    float slo = (a0.y + a0.z) + (b0.y + b0.z);
    float shi = (a1.y + a1.z) + (b1.y + b1.z);
    slo = fmaxf(slo, __shfl_xor_sync(0xffffffffu, slo, 1));
    shi = fmaxf(shi, __shfl_xor_sync(0xffffffffu, shi, 1));

    __shared__ float sm[2][4][32];
    if ((lane & 1) == 0) {
        int j = lane >> 1;
        sm[half][ii][j]      = slo;
        sm[half][ii][j + 16] = shi;
    }
    __syncthreads();

    if (tid < 128) {
        int j  = tid & 31;
        int iw = tid >> 5;
        float m = fmaxf(sm[0][iw][j], sm[1][iw][j]);
        g_p[((size_t)(n * C_CH + c) * QS + it * 4 + iw) * QS + j] = 0.25f * m;
    }
}

// ---------------------------------------------------------------------------
// Kernel B: smem-tiled f32x2 matmul (R11 version, unchanged)
// ---------------------------------------------------------------------------
__global__ void __launch_bounds__(256) kB(const float* __restrict__ w1,
                                          const float* __restrict__ b1,
                                          const float* __restrict__ ws,
                                          const float* __restrict__ bs) {
    __shared__ float p_sm[C_CH][256];
    __shared__ float w_sm1[32][32];
    __shared__ float w_sms[32][32];

    const int og    = blockIdx.x;
    const int ptile = blockIdx.y;
    const int n     = blockIdx.z;
    const int t     = threadIdx.x;
    const int lane  = t & 31;
    const int osub  = t >> 5;

    const float4* pg = (const float4*)(g_p + (size_t)n * (C_CH * QS * QS) + ptile * 256);
#pragma unroll
    for (int v = 0; v < 8; v++) {
        int idx = v * 256 + t;
        int c  = idx >> 6;
        int f4 = idx & 63;
        *(float4*)&p_sm[c][4 * f4] = __ldg(pg + c * (1024 / 4) + f4);
    }
    {
        int ol = t >> 3;
        int cq = t & 7;
        *(float4*)&w_sm1[ol][4 * cq] = __ldg((const float4*)(w1 + (og * 32 + ol) * C_CH) + cq);
        *(float4*)&w_sms[ol][4 * cq] = __ldg((const float4*)(ws + (og * 32 + ol) * C_CH) + cq);
    }
    __syncthreads();

    u64 acc1[4][4], acc2[4][4];
#pragma unroll
    for (int m = 0; m < 4; m++)
#pragma unroll
        for (int i = 0; i < 4; i++) { acc1[m][i] = 0; acc2[m][i] = 0; }

#pragma unroll
    for (int c = 0; c < C_CH; c++) {
        u64 p2[4];
#pragma unroll
        for (int i = 0; i < 4; i++)
            p2[i] = *(const u64*)&p_sm[c][2 * (lane + 32 * i)];
#pragma unroll
        for (int m = 0; m < 4; m++) {
            int ol = osub * 4 + m;
            float w1c = w_sm1[ol][c];
            float wsc = w_sms[ol][c];
            u64 w12 = pk2(w1c, w1c);
            u64 ws2 = pk2(wsc, wsc);
#pragma unroll
            for (int i = 0; i < 4; i++) {
                acc1[m][i] = ffma2(w12, p2[i], acc1[m][i]);
                acc2[m][i] = ffma2(ws2, p2[i], acc2[m][i]);
            }
        }
    }

    float* yb = g_y + (size_t)n * (OCH * QS * QS) + (size_t)og * 32 * 1024 + ptile * 256;
#pragma unroll
    for (int m = 0; m < 4; m++) {
        int ol = osub * 4 + m;
        int o  = og * 32 + ol;
        float bb1 = __ldg(b1 + o);
        float bbs = __ldg(bs + o);
#pragma unroll
        for (int i = 0; i < 4; i++) {
            float2 d1 = unpk2(acc1[m][i]);
            float2 d2 = unpk2(acc2[m][i]);
            float z0 = d1.x + bb1, z1 = d1.y + bb1;
            float a0 = (z0 >= 0.f) ? z0 : 0.2f * z0;
            float a1 = (z1 >= 0.f) ? z1 : 0.2f * z1;
            float2 r = make_float2(a0 + d2.x + bbs, a1 + d2.y + bbs);
            *(float2*)&yb[ol * 1024 + 2 * (lane + 32 * i)] = r;
        }
    }
}

__global__ void kPad() {}

// ---------------------------------------------------------------------------
// Kernel C: f32x2 column-pair version; window now via 3 aligned LDS.64
// (pairs (c0-2,c0-1),(c0,c0+1),(c0+2,c0+3)); launch_bounds(128,8) for 50% occ.
// ---------------------------------------------------------------------------
__global__ void __launch_bounds__(128, 8) kC(const float* __restrict__ fm,
                                             float* __restrict__ out) {
    __shared__ float fmt[18 * FSTR];
    __shared__ __align__(16) float yt[4][32][12];

    const int tt = blockIdx.x;
    const int c  = blockIdx.y;
    const int n  = blockIdx.z;
    const int j  = threadIdx.x;          // 0..127, columns (2j, 2j+1)
    const int h0 = tt * 16;
    const int crBase = 2 * tt - 1;

    const float4* fbase4 = (const float4*)(fm + ((size_t)(n * C_CH + c) * HW) * HW);
    const float4 z4 = make_float4(0.f, 0.f, 0.f, 0.f);
#pragma unroll
    for (int v = 0; v < 9; v++) {
        int idx = v * 128 + j;
        int r = idx >> 6;
        int q = idx & 63;
        int gh = h0 - 1 + r;
        float4 val = (gh >= 0 && gh < HW) ? __ldg(fbase4 + gh * (HW / 4) + q) : z4;
        *(float4*)&fmt[r * FSTR + 4 + 4 * q] = val;
    }
    if (j < 36) {
        int r = j >> 1;
        fmt[r * FSTR + 3 + 257 * (j & 1)] = 0.f;
    }

    const float* ybase = g_y + (size_t)(n * OCH + c * KS2) * (QS * QS);
#pragma unroll
    for (int v = 0; v < 3; v++) {
        int idx = v * 128 + j;
        if (idx < 288) {
            int q  = idx & 7;
            int rk = idx >> 3;
            int r  = rk / KS2;
            int k  = rk - r * KS2;
            int cr = min(max(crBase + r, 0), QS - 1);
            float4 s = __ldg((const float4*)(ybase + k * (QS * QS) + cr * QS) + q);
            int col = 4 * q;
            yt[r][col + 0][k] = s.x;
            yt[r][col + 1][k] = s.y;
            yt[r][col + 2][k] = s.z;
            yt[r][col + 3][k] = s.w;
        }
    }
    __syncthreads();

    const int c0 = 2 * j;
    int ix0 = (c0 - 4) >> 3;
    float wx0 = (float)c0 * 0.125f - 0.4375f - (float)ix0;
    float wx1 = wx0 + 0.125f;
    const int jx0 = max(ix0, 0);
    const int jx1 = min(ix0 + 1, QS - 1);

    u64 hl2[KS2], df2[KS2];
    auto loadHL2 = [&](int r, u64* dst) {
        const float4* pa = (const float4*)yt[r][jx0];
        const float4* pb = (const float4*)yt[r][jx1];
        float4 a0 = pa[0], a1 = pa[1];
        float4 b0 = pb[0], b1 = pb[1];
        float  a8 = yt[r][jx0][8];
        float  b8 = yt[r][jx1][8];
        float ta[KS2];
        ta[0] = b0.x - a0.x; ta[1] = b0.y - a0.y; ta[2] = b0.z - a0.z;
        ta[3] = b0.w - a0.w; ta[4] = b1.x - a1.x; ta[5] = b1.y - a1.y;
        ta[6] = b1.z - a1.z; ta[7] = b1.w - a1.w; ta[8] = b8 - a8;
        float av[KS2];
        av[0] = a0.x; av[1] = a0.y; av[2] = a0.z; av[3] = a0.w;
        av[4] = a1.x; av[5] = a1.y; av[6] = a1.z; av[7] = a1.w; av[8] = a8;
#pragma unroll
        for (int k = 0; k < KS2; k++)
            dst[k] = pk2(fmaf(wx0, ta[k], av[k]), fmaf(wx1, ta[k], av[k]));
    };

    loadHL2(0, hl2);
    loadHL2(1, df2);
#pragma unroll
    for (int k = 0; k < KS2; k++) df2[k] = fadd2(df2[k], fneg2(hl2[k]));

    auto advance = [&](int newRow) {
#pragma unroll
        for (int k = 0; k < KS2; k++) hl2[k] = fadd2(hl2[k], df2[k]);
        loadHL2(newRow, df2);
#pragma unroll
        for (int k = 0; k < KS2; k++) df2[k] = fadd2(df2[k], fneg2(hl2[k]));
    };

    // ---- window: 3 aligned LDS.64 per row ----
    // float2 pairs at word offsets r*FSTR + {2,4,6} + c0 (all even -> 8B aligned)
    const float2* wbase = (const float2*)fmt + 1 + j;   // word 2+c0 of row 0
    auto loadWin = [&](int r, u64* Pr) {
        const float2* bp = wbase + r * (FSTR / 2);
        float2 A = bp[0], B = bp[1], C = bp[2];
        Pr[0] = pk2(A.y, B.x);   // (f[c0-1], f[c0])
        Pr[1] = pk2(B.x, B.y);   // (f[c0],   f[c0+1])
        Pr[2] = pk2(B.y, C.x);   // (f[c0+1], f[c0+2])
    };

    u64 P[3][3];
    loadWin(0, P[0]);
    loadWin(1, P[1]);

    float2* ob = (float2*)(out + (((size_t)(n * C_CH + c) * HW + h0) * HW) + c0);

    auto doRow = [&](int hh, float wy) {
        loadWin(hh + 2, P[2]);
        u64 wy2 = pk2(wy, wy);
        u64 accA = 0, accB = 0;
#pragma unroll
        for (int dy = 0; dy < 3; dy++) {
#pragma unroll
            for (int dx = 0; dx < 3; dx++) {
                int k = dy * 3 + dx;
                u64 ft = ffma2(wy2, df2[k], hl2[k]);
                if (k < 5) accA = ffma2(ft, P[dy][dx], accA);
                else       accB = ffma2(ft, P[dy][dx], accB);
            }
        }
        ob[hh * (HW / 2)] = unpk2(fadd2(accA, accB));
#pragma unroll
        for (int d = 0; d < 3; d++) { P[0][d] = P[1][d]; P[1][d] = P[2][d]; }
    };

#pragma unroll
    for (int hh = 0; hh < 4; hh++)   doRow(hh, (float)hh * 0.125f + 0.5625f);
    advance(2);
#pragma unroll
    for (int hh = 4; hh < 12; hh++)  doRow(hh, (float)hh * 0.125f - 0.4375f);
    advance(3);
#pragma unroll
    for (int hh = 12; hh < 16; hh++) doRow(hh, (float)hh * 0.125f - 1.4375f);
}

// ---------------------------------------------------------------------------
extern "C" void kernel_launch(void* const* d_in, const int* in_sizes, int n_in,
                              void* d_out, int out_size) {
    const float* psf = (const float*)d_in[0];
    const float* fm  = (const float*)d_in[1];
    const float* w1  = (const float*)d_in[2];
    const float* b1  = (const float*)d_in[3];
    const float* ws  = (const float*)d_in[4];
    const float* bs  = (const float*)d_in[5];
    float* out = (float*)d_out;

    kA<<<1024, 256>>>(psf);
    dim3 gb(9, 4, NB);
    kB<<<gb, 256>>>(w1, b1, ws, bs);
    kPad<<<1, 32>>>();
    dim3 gc(16, C_CH, NB);
    kC<<<gc, 128>>>(fm, out);
}

// round 13
// speedup vs baseline: 1.0809x; 1.0809x over previous
#include <cuda_runtime.h>

#define C_CH 32
#define HW   256
#define KS2  9
#define OCH  288
#define QS   32
#define NB   4

#define FSTR 264   // fmt row stride (words); interior cols 4..259 (16B aligned)

__device__ float g_p[NB * C_CH * QS * QS];   // [n][c][32][32]
__device__ float g_y[NB * OCH * QS * QS];    // [n][o][32][32]

// ---- f32x2 packed helpers (sm_103a native) ----
typedef unsigned long long u64;
__device__ __forceinline__ u64 pk2(float lo, float hi) {
    u64 r; asm("mov.b64 %0, {%1, %2};" : "=l"(r) : "f"(lo), "f"(hi)); return r;
}
__device__ __forceinline__ float2 unpk2(u64 v) {
    float2 f; asm("mov.b64 {%0, %1}, %2;" : "=f"(f.x), "=f"(f.y) : "l"(v)); return f;
}
__device__ __forceinline__ u64 ffma2(u64 a, u64 b, u64 c) {
    u64 d; asm("fma.rn.f32x2 %0, %1, %2, %3;" : "=l"(d) : "l"(a), "l"(b), "l"(c)); return d;
}
__device__ __forceinline__ u64 fadd2(u64 a, u64 b) {
    u64 d; asm("add.rn.f32x2 %0, %1, %2;" : "=l"(d) : "l"(a), "l"(b)); return d;
}
__device__ __forceinline__ u64 fneg2(u64 a) { return a ^ 0x8000000080000000ULL; }

// ---------------------------------------------------------------------------
// Kernel A: psf -> bilinear 1/4 -> maxpool2 -> g_p  (unchanged)
// ---------------------------------------------------------------------------
__global__ void __launch_bounds__(256) kA(const float* __restrict__ psf) {
    const int b  = blockIdx.x;
    const int it = b & 7;
    const int c  = (b >> 3) & 31;
    const int n  = b >> 8;
    const int tid  = threadIdx.x;
    const int warp = tid >> 5;
    const int lane = tid & 31;
    const int ii   = warp >> 1;
    const int half = warp & 1;
    const int i = it * 4 + ii;

    const float4* base = (const float4*)(psf + ((size_t)(n * C_CH + c) * HW) * HW);
    const int r0 = 8 * i + 1 + 4 * half;
    const float4* p0 = base + r0 * (HW / 4);
    const float4* p1 = p0 + (HW / 4);

    float4 a0 = __ldg(p0 + lane);
    float4 a1 = __ldg(p0 + 32 + lane);
    float4 b0 = __ldg(p1 + lane);
    float4 b1 = __ldg(p1 + 32 + lane);

    float slo = (a0.y + a0.z) + (b0.y + b0.z);
    float shi = (a1.y + a1.z) + (b1.y + b1.z);
    slo = fmaxf(slo, __shfl_xor_sync(0xffffffffu, slo, 1));
    shi = fmaxf(shi, __shfl_xor_sync(0xffffffffu, shi, 1));

    __shared__ float sm[2][4][32];
    if ((lane & 1) == 0) {
        int j = lane >> 1;
        sm[half][ii][j]      = slo;
        sm[half][ii][j + 16] = shi;
    }
    __syncthreads();

    if (tid < 128) {
        int j  = tid & 31;
        int iw = tid >> 5;
        float m = fmaxf(sm[0][iw][j], sm[1][iw][j]);
        g_p[((size_t)(n * C_CH + c) * QS + it * 4 + iw) * QS + j] = 0.25f * m;
    }
}

// ---------------------------------------------------------------------------
// Kernel B: smem-tiled f32x2 matmul (R11 version, unchanged)
// ---------------------------------------------------------------------------
__global__ void __launch_bounds__(256) kB(const float* __restrict__ w1,
                                          const float* __restrict__ b1,
                                          const float* __restrict__ ws,
                                          const float* __restrict__ bs) {
    __shared__ float p_sm[C_CH][256];
    __shared__ float w_sm1[32][32];
    __shared__ float w_sms[32][32];

    const int og    = blockIdx.x;
    const int ptile = blockIdx.y;
    const int n     = blockIdx.z;
    const int t     = threadIdx.x;
    const int lane  = t & 31;
    const int osub  = t >> 5;

    const float4* pg = (const float4*)(g_p + (size_t)n * (C_CH * QS * QS) + ptile * 256);
#pragma unroll
    for (int v = 0; v < 8; v++) {
        int idx = v * 256 + t;
        int c  = idx >> 6;
        int f4 = idx & 63;
        *(float4*)&p_sm[c][4 * f4] = __ldg(pg + c * (1024 / 4) + f4);
    }
    {
        int ol = t >> 3;
        int cq = t & 7;
        *(float4*)&w_sm1[ol][4 * cq] = __ldg((const float4*)(w1 + (og * 32 + ol) * C_CH) + cq);
        *(float4*)&w_sms[ol][4 * cq] = __ldg((const float4*)(ws + (og * 32 + ol) * C_CH) + cq);
    }
    __syncthreads();

    u64 acc1[4][4], acc2[4][4];
#pragma unroll
    for (int m = 0; m < 4; m++)
#pragma unroll
        for (int i = 0; i < 4; i++) { acc1[m][i] = 0; acc2[m][i] = 0; }

#pragma unroll
    for (int c = 0; c < C_CH; c++) {
        u64 p2[4];
#pragma unroll
        for (int i = 0; i < 4; i++)
            p2[i] = *(const u64*)&p_sm[c][2 * (lane + 32 * i)];
#pragma unroll
        for (int m = 0; m < 4; m++) {
            int ol = osub * 4 + m;
            float w1c = w_sm1[ol][c];
            float wsc = w_sms[ol][c];
            u64 w12 = pk2(w1c, w1c);
            u64 ws2 = pk2(wsc, wsc);
#pragma unroll
            for (int i = 0; i < 4; i++) {
                acc1[m][i] = ffma2(w12, p2[i], acc1[m][i]);
                acc2[m][i] = ffma2(ws2, p2[i], acc2[m][i]);
            }
        }
    }

    float* yb = g_y + (size_t)n * (OCH * QS * QS) + (size_t)og * 32 * 1024 + ptile * 256;
#pragma unroll
    for (int m = 0; m < 4; m++) {
        int ol = osub * 4 + m;
        int o  = og * 32 + ol;
        float bb1 = __ldg(b1 + o);
        float bbs = __ldg(bs + o);
#pragma unroll
        for (int i = 0; i < 4; i++) {
            float2 d1 = unpk2(acc1[m][i]);
            float2 d2 = unpk2(acc2[m][i]);
            float z0 = d1.x + bb1, z1 = d1.y + bb1;
            float a0 = (z0 >= 0.f) ? z0 : 0.2f * z0;
            float a1 = (z1 >= 0.f) ? z1 : 0.2f * z1;
            float2 r = make_float2(a0 + d2.x + bbs, a1 + d2.y + bbs);
            *(float2*)&yb[ol * 1024 + 2 * (lane + 32 * i)] = r;
        }
    }
}

// ---------------------------------------------------------------------------
// Kernel C: f32x2 column-pair version (R11 verbatim — best measured: 17.1us).
// No launch_bounds cap; 4x scalar LDS window loads (independent, no packing
// dependency chain).
// ---------------------------------------------------------------------------
__global__ void __launch_bounds__(128) kC(const float* __restrict__ fm,
                                          float* __restrict__ out) {
    __shared__ float fmt[18 * FSTR];
    __shared__ __align__(16) float yt[4][32][12];

    const int tt = blockIdx.x;
    const int c  = blockIdx.y;
    const int n  = blockIdx.z;
    const int j  = threadIdx.x;          // 0..127, columns (2j, 2j+1)
    const int h0 = tt * 16;
    const int crBase = 2 * tt - 1;

    const float4* fbase4 = (const float4*)(fm + ((size_t)(n * C_CH + c) * HW) * HW);
    const float4 z4 = make_float4(0.f, 0.f, 0.f, 0.f);
#pragma unroll
    for (int v = 0; v < 9; v++) {
        int idx = v * 128 + j;
        int r = idx >> 6;
        int q = idx & 63;
        int gh = h0 - 1 + r;
        float4 val = (gh >= 0 && gh < HW) ? __ldg(fbase4 + gh * (HW / 4) + q) : z4;
        *(float4*)&fmt[r * FSTR + 4 + 4 * q] = val;
    }
    if (j < 36) {
        int r = j >> 1;
        fmt[r * FSTR + 3 + 257 * (j & 1)] = 0.f;
    }

    const float* ybase = g_y + (size_t)(n * OCH + c * KS2) * (QS * QS);
#pragma unroll
    for (int v = 0; v < 3; v++) {
        int idx = v * 128 + j;
        if (idx < 288) {
            int q  = idx & 7;
            int rk = idx >> 3;
            int r  = rk / KS2;
            int k  = rk - r * KS2;
            int cr = min(max(crBase + r, 0), QS - 1);
            float4 s = __ldg((const float4*)(ybase + k * (QS * QS) + cr * QS) + q);
            int col = 4 * q;
            yt[r][col + 0][k] = s.x;
            yt[r][col + 1][k] = s.y;
            yt[r][col + 2][k] = s.z;
            yt[r][col + 3][k] = s.w;
        }
    }
    __syncthreads();

    const int c0 = 2 * j;
    int ix0 = (c0 - 4) >> 3;
    float wx0 = (float)c0 * 0.125f - 0.4375f - (float)ix0;
    float wx1 = wx0 + 0.125f;
    const int jx0 = max(ix0, 0);
    const int jx1 = min(ix0 + 1, QS - 1);

    u64 hl2[KS2], df2[KS2];
    auto loadHL2 = [&](int r, u64* dst) {
        const float4* pa = (const float4*)yt[r][jx0];
        const float4* pb = (const float4*)yt[r][jx1];
        float4 a0 = pa[0], a1 = pa[1];
        float4 b0 = pb[0], b1 = pb[1];
        float  a8 = yt[r][jx0][8];
        float  b8 = yt[r][jx1][8];
        float ta[KS2];
        ta[0] = b0.x - a0.x; ta[1] = b0.y - a0.y; ta[2] = b0.z - a0.z;
        ta[3] = b0.w - a0.w; ta[4] = b1.x - a1.x; ta[5] = b1.y - a1.y;
        ta[6] = b1.z - a1.z; ta[7] = b1.w - a1.w; ta[8] = b8 - a8;
        float av[KS2];
        av[0] = a0.x; av[1] = a0.y; av[2] = a0.z; av[3] = a0.w;
        av[4] = a1.x; av[5] = a1.y; av[6] = a1.z; av[7] = a1.w; av[8] = a8;
#pragma unroll
        for (int k = 0; k < KS2; k++)
            dst[k] = pk2(fmaf(wx0, ta[k], av[k]), fmaf(wx1, ta[k], av[k]));
    };

    loadHL2(0, hl2);
    loadHL2(1, df2);
#pragma unroll
    for (int k = 0; k < KS2; k++) df2[k] = fadd2(df2[k], fneg2(hl2[k]));

    auto advance = [&](int newRow) {
#pragma unroll
        for (int k = 0; k < KS2; k++) hl2[k] = fadd2(hl2[k], df2[k]);
        loadHL2(newRow, df2);
#pragma unroll
        for (int k = 0; k < KS2; k++) df2[k] = fadd2(df2[k], fneg2(hl2[k]));
    };

    const float* fcol = fmt + 3 + c0;
    u64 P[3][3];
#pragma unroll
    for (int r = 0; r < 2; r++) {
        float f0 = fcol[r * FSTR + 0], f1 = fcol[r * FSTR + 1];
        float f2 = fcol[r * FSTR + 2], f3 = fcol[r * FSTR + 3];
        P[r][0] = pk2(f0, f1); P[r][1] = pk2(f1, f2); P[r][2] = pk2(f2, f3);
    }

    float2* ob = (float2*)(out + (((size_t)(n * C_CH + c) * HW + h0) * HW) + c0);

    auto doRow = [&](int hh, float wy) {
        {
            float f0 = fcol[(hh + 2) * FSTR + 0], f1 = fcol[(hh + 2) * FSTR + 1];
            float f2 = fcol[(hh + 2) * FSTR + 2], f3 = fcol[(hh + 2) * FSTR + 3];
            P[2][0] = pk2(f0, f1); P[2][1] = pk2(f1, f2); P[2][2] = pk2(f2, f3);
        }
        u64 wy2 = pk2(wy, wy);
        u64 accA = 0, accB = 0;
#pragma unroll
        for (int dy = 0; dy < 3; dy++) {
#pragma unroll
            for (int dx = 0; dx < 3; dx++) {
                int k = dy * 3 + dx;
                u64 ft = ffma2(wy2, df2[k], hl2[k]);
                if (k < 5) accA = ffma2(ft, P[dy][dx], accA);
                else       accB = ffma2(ft, P[dy][dx], accB);
            }
        }
        ob[hh * (HW / 2)] = unpk2(fadd2(accA, accB));
#pragma unroll
        for (int d = 0; d < 3; d++) { P[0][d] = P[1][d]; P[1][d] = P[2][d]; }
    };

#pragma unroll
    for (int hh = 0; hh < 4; hh++)   doRow(hh, (float)hh * 0.125f + 0.5625f);
    advance(2);
#pragma unroll
    for (int hh = 4; hh < 12; hh++)  doRow(hh, (float)hh * 0.125f - 0.4375f);
    advance(3);
#pragma unroll
    for (int hh = 12; hh < 16; hh++) doRow(hh, (float)hh * 0.125f - 1.4375f);
}

// ---------------------------------------------------------------------------
extern "C" void kernel_launch(void* const* d_in, const int* in_sizes, int n_in,
                              void* d_out, int out_size) {
    const float* psf = (const float*)d_in[0];
    const float* fm  = (const float*)d_in[1];
    const float* w1  = (const float*)d_in[2];
    const float* b1  = (const float*)d_in[3];
    const float* ws  = (const float*)d_in[4];
    const float* bs  = (const float*)d_in[5];
    float* out = (float*)d_out;

    kA<<<1024, 256>>>(psf);
    dim3 gb(9, 4, NB);
    kB<<<gb, 256>>>(w1, b1, ws, bs);
    dim3 gc(16, C_CH, NB);
    kC<<<gc, 128>>>(fm, out);
}

// round 14
// speedup vs baseline: 1.0976x; 1.0154x over previous
#include <cuda_runtime.h>

#define C_CH 32
#define HW   256
#define KS2  9
#define OCH  288
#define QS   32
#define NB   4

#define FSTR 264   // fmt row stride (words); interior cols 4..259 (16B aligned)

__device__ float g_p[NB * C_CH * QS * QS];   // [n][c][32][32]
__device__ float g_y[NB * OCH * QS * QS];    // [n][o][32][32]

// ---- f32x2 packed helpers (sm_103a native) ----
typedef unsigned long long u64;
__device__ __forceinline__ u64 pk2(float lo, float hi) {
    u64 r; asm("mov.b64 %0, {%1, %2};" : "=l"(r) : "f"(lo), "f"(hi)); return r;
}
__device__ __forceinline__ float2 unpk2(u64 v) {
    float2 f; asm("mov.b64 {%0, %1}, %2;" : "=f"(f.x), "=f"(f.y) : "l"(v)); return f;
}
__device__ __forceinline__ u64 ffma2(u64 a, u64 b, u64 c) {
    u64 d; asm("fma.rn.f32x2 %0, %1, %2, %3;" : "=l"(d) : "l"(a), "l"(b), "l"(c)); return d;
}
__device__ __forceinline__ u64 fadd2(u64 a, u64 b) {
    u64 d; asm("add.rn.f32x2 %0, %1, %2;" : "=l"(d) : "l"(a), "l"(b)); return d;
}
__device__ __forceinline__ u64 fneg2(u64 a) { return a ^ 0x8000000080000000ULL; }

// ---------------------------------------------------------------------------
// Kernel A: psf -> bilinear 1/4 -> maxpool2 -> g_p.
// Triggers PDL completion after its stores.
// ---------------------------------------------------------------------------
__global__ void __launch_bounds__(256) kA(const float* __restrict__ psf) {
    const int b  = blockIdx.x;
    const int it = b & 7;
    const int c  = (b >> 3) & 31;
    const int n  = b >> 8;
    const int tid  = threadIdx.x;
    const int warp = tid >> 5;
    const int lane = tid & 31;
    const int ii   = warp >> 1;
    const int half = warp & 1;
    const int i = it * 4 + ii;

    const float4* base = (const float4*)(psf + ((size_t)(n * C_CH + c) * HW) * HW);
    const int r0 = 8 * i + 1 + 4 * half;
    const float4* p0 = base + r0 * (HW / 4);
    const float4* p1 = p0 + (HW / 4);

    float4 a0 = __ldg(p0 + lane);
    float4 a1 = __ldg(p0 + 32 + lane);
    float4 b0 = __ldg(p1 + lane);
    float4 b1 = __ldg(p1 + 32 + lane);

    float slo = (a0.y + a0.z) + (b0.y + b0.z);
    float shi = (a1.y + a1.z) + (b1.y + b1.z);
    slo = fmaxf(slo, __shfl_xor_sync(0xffffffffu, slo, 1));
    shi = fmaxf(shi, __shfl_xor_sync(0xffffffffu, shi, 1));

    __shared__ float sm[2][4][32];
    if ((lane & 1) == 0) {
        int j = lane >> 1;
        sm[half][ii][j]      = slo;
        sm[half][ii][j + 16] = shi;
    }
    __syncthreads();

    if (tid < 128) {
        int j  = tid & 31;
        int iw = tid >> 5;
        float m = fmaxf(sm[0][iw][j], sm[1][iw][j]);
        g_p[((size_t)(n * C_CH + c) * QS + it * 4 + iw) * QS + j] = 0.25f * m;
    }
    cudaTriggerProgrammaticLaunchCompletion();
}

// ---------------------------------------------------------------------------
// Kernel B: smem-tiled f32x2 matmul. PDL: stage weights (independent of kA),
// gridDepSync, then stage p. Triggers completion after g_y stores.
// ---------------------------------------------------------------------------
__global__ void __launch_bounds__(256) kB(const float* __restrict__ w1,
                                          const float* __restrict__ b1,
                                          const float* __restrict__ bs_w,
                                          const float* __restrict__ bs_b) {
    __shared__ float p_sm[C_CH][256];
    __shared__ float w_sm1[32][32];
    __shared__ float w_sms[32][32];

    const int og    = blockIdx.x;
    const int ptile = blockIdx.y;
    const int n     = blockIdx.z;
    const int t     = threadIdx.x;
    const int lane  = t & 31;
    const int osub  = t >> 5;

    // ---- independent prologue: weight slice staging ----
    {
        int ol = t >> 3;
        int cq = t & 7;
        *(float4*)&w_sm1[ol][4 * cq] = __ldg((const float4*)(w1 + (og * 32 + ol) * C_CH) + cq);
        *(float4*)&w_sms[ol][4 * cq] = __ldg((const float4*)(bs_w + (og * 32 + ol) * C_CH) + cq);
    }

    // ---- wait for kA's g_p ----
    cudaGridDependencySynchronize();

    const float4* pg = (const float4*)(g_p + (size_t)n * (C_CH * QS * QS) + ptile * 256);
#pragma unroll
    for (int v = 0; v < 8; v++) {
        int idx = v * 256 + t;
        int c  = idx >> 6;
        int f4 = idx & 63;
        *(float4*)&p_sm[c][4 * f4] = __ldg(pg + c * (1024 / 4) + f4);
    }
    __syncthreads();

    u64 acc1[4][4], acc2[4][4];
#pragma unroll
    for (int m = 0; m < 4; m++)
#pragma unroll
        for (int i = 0; i < 4; i++) { acc1[m][i] = 0; acc2[m][i] = 0; }

#pragma unroll
    for (int c = 0; c < C_CH; c++) {
        u64 p2[4];
#pragma unroll
        for (int i = 0; i < 4; i++)
            p2[i] = *(const u64*)&p_sm[c][2 * (lane + 32 * i)];
#pragma unroll
        for (int m = 0; m < 4; m++) {
            int ol = osub * 4 + m;
            float w1c = w_sm1[ol][c];
            float wsc = w_sms[ol][c];
            u64 w12 = pk2(w1c, w1c);
            u64 ws2 = pk2(wsc, wsc);
#pragma unroll
            for (int i = 0; i < 4; i++) {
                acc1[m][i] = ffma2(w12, p2[i], acc1[m][i]);
                acc2[m][i] = ffma2(ws2, p2[i], acc2[m][i]);
            }
        }
    }

    float* yb = g_y + (size_t)n * (OCH * QS * QS) + (size_t)og * 32 * 1024 + ptile * 256;
#pragma unroll
    for (int m = 0; m < 4; m++) {
        int ol = osub * 4 + m;
        int o  = og * 32 + ol;
        float bb1 = __ldg(b1 + o);
        float bbs = __ldg(bs_b + o);
#pragma unroll
        for (int i = 0; i < 4; i++) {
            float2 d1 = unpk2(acc1[m][i]);
            float2 d2 = unpk2(acc2[m][i]);
            float z0 = d1.x + bb1, z1 = d1.y + bb1;
            float a0 = (z0 >= 0.f) ? z0 : 0.2f * z0;
            float a1 = (z1 >= 0.f) ? z1 : 0.2f * z1;
            float2 r = make_float2(a0 + d2.x + bbs, a1 + d2.y + bbs);
            *(float2*)&yb[ol * 1024 + 2 * (lane + 32 * i)] = r;
        }
    }
    cudaTriggerProgrammaticLaunchCompletion();
}

// ---------------------------------------------------------------------------
// Kernel C: f32x2 column-pair FAC (R11 math, unchanged). PDL: stage fmt
// (independent of kB), gridDepSync, then stage yt from g_y.
// ---------------------------------------------------------------------------
__global__ void __launch_bounds__(128) kC(const float* __restrict__ fm,
                                          float* __restrict__ out) {
    __shared__ float fmt[18 * FSTR];
    __shared__ __align__(16) float yt[4][32][12];

    const int tt = blockIdx.x;
    const int c  = blockIdx.y;
    const int n  = blockIdx.z;
    const int j  = threadIdx.x;          // 0..127, columns (2j, 2j+1)
    const int h0 = tt * 16;
    const int crBase = 2 * tt - 1;

    // ---- independent prologue: featuremap tile staging ----
    const float4* fbase4 = (const float4*)(fm + ((size_t)(n * C_CH + c) * HW) * HW);
    const float4 z4 = make_float4(0.f, 0.f, 0.f, 0.f);
#pragma unroll
    for (int v = 0; v < 9; v++) {
        int idx = v * 128 + j;
        int r = idx >> 6;
        int q = idx & 63;
        int gh = h0 - 1 + r;
        float4 val = (gh >= 0 && gh < HW) ? __ldg(fbase4 + gh * (HW / 4) + q) : z4;
        *(float4*)&fmt[r * FSTR + 4 + 4 * q] = val;
    }
    if (j < 36) {
        int r = j >> 1;
        fmt[r * FSTR + 3 + 257 * (j & 1)] = 0.f;
    }

    // ---- wait for kB's g_y ----
    cudaGridDependencySynchronize();

    const float* ybase = g_y + (size_t)(n * OCH + c * KS2) * (QS * QS);
#pragma unroll
    for (int v = 0; v < 3; v++) {
        int idx = v * 128 + j;
        if (idx < 288) {
            int q  = idx & 7;
            int rk = idx >> 3;
            int r  = rk / KS2;
            int k  = rk - r * KS2;
            int cr = min(max(crBase + r, 0), QS - 1);
            float4 s = __ldg((const float4*)(ybase + k * (QS * QS) + cr * QS) + q);
            int col = 4 * q;
            yt[r][col + 0][k] = s.x;
            yt[r][col + 1][k] = s.y;
            yt[r][col + 2][k] = s.z;
            yt[r][col + 3][k] = s.w;
        }
    }
    __syncthreads();

    const int c0 = 2 * j;
    int ix0 = (c0 - 4) >> 3;
    float wx0 = (float)c0 * 0.125f - 0.4375f - (float)ix0;
    float wx1 = wx0 + 0.125f;
    const int jx0 = max(ix0, 0);
    const int jx1 = min(ix0 + 1, QS - 1);

    u64 hl2[KS2], df2[KS2];
    auto loadHL2 = [&](int r, u64* dst) {
        const float4* pa = (const float4*)yt[r][jx0];
        const float4* pb = (const float4*)yt[r][jx1];
        float4 a0 = pa[0], a1 = pa[1];
        float4 b0 = pb[0], b1 = pb[1];
        float  a8 = yt[r][jx0][8];
        float  b8 = yt[r][jx1][8];
        float ta[KS2];
        ta[0] = b0.x - a0.x; ta[1] = b0.y - a0.y; ta[2] = b0.z - a0.z;
        ta[3] = b0.w - a0.w; ta[4] = b1.x - a1.x; ta[5] = b1.y - a1.y;
        ta[6] = b1.z - a1.z; ta[7] = b1.w - a1.w; ta[8] = b8 - a8;
        float av[KS2];
        av[0] = a0.x; av[1] = a0.y; av[2] = a0.z; av[3] = a0.w;
        av[4] = a1.x; av[5] = a1.y; av[6] = a1.z; av[7] = a1.w; av[8] = a8;
#pragma unroll
        for (int k = 0; k < KS2; k++)
            dst[k] = pk2(fmaf(wx0, ta[k], av[k]), fmaf(wx1, ta[k], av[k]));
    };

    loadHL2(0, hl2);
    loadHL2(1, df2);
#pragma unroll
    for (int k = 0; k < KS2; k++) df2[k] = fadd2(df2[k], fneg2(hl2[k]));

    auto advance = [&](int newRow) {
#pragma unroll
        for (int k = 0; k < KS2; k++) hl2[k] = fadd2(hl2[k], df2[k]);
        loadHL2(newRow, df2);
#pragma unroll
        for (int k = 0; k < KS2; k++) df2[k] = fadd2(df2[k], fneg2(hl2[k]));
    };

    const float* fcol = fmt + 3 + c0;
    u64 P[3][3];
#pragma unroll
    for (int r = 0; r < 2; r++) {
        float f0 = fcol[r * FSTR + 0], f1 = fcol[r * FSTR + 1];
        float f2 = fcol[r * FSTR + 2], f3 = fcol[r * FSTR + 3];
        P[r][0] = pk2(f0, f1); P[r][1] = pk2(f1, f2); P[r][2] = pk2(f2, f3);
    }

    float2* ob = (float2*)(out + (((size_t)(n * C_CH + c) * HW + h0) * HW) + c0);

    auto doRow = [&](int hh, float wy) {
        {
            float f0 = fcol[(hh + 2) * FSTR + 0], f1 = fcol[(hh + 2) * FSTR + 1];
            float f2 = fcol[(hh + 2) * FSTR + 2], f3 = fcol[(hh + 2) * FSTR + 3];
            P[2][0] = pk2(f0, f1); P[2][1] = pk2(f1, f2); P[2][2] = pk2(f2, f3);
        }
        u64 wy2 = pk2(wy, wy);
        u64 accA = 0, accB = 0;
#pragma unroll
        for (int dy = 0; dy < 3; dy++) {
#pragma unroll
            for (int dx = 0; dx < 3; dx++) {
                int k = dy * 3 + dx;
                u64 ft = ffma2(wy2, df2[k], hl2[k]);
                if (k < 5) accA = ffma2(ft, P[dy][dx], accA);
                else       accB = ffma2(ft, P[dy][dx], accB);
            }
        }
        ob[hh * (HW / 2)] = unpk2(fadd2(accA, accB));
#pragma unroll
        for (int d = 0; d < 3; d++) { P[0][d] = P[1][d]; P[1][d] = P[2][d]; }
    };

#pragma unroll
    for (int hh = 0; hh < 4; hh++)   doRow(hh, (float)hh * 0.125f + 0.5625f);
    advance(2);
#pragma unroll
    for (int hh = 4; hh < 12; hh++)  doRow(hh, (float)hh * 0.125f - 0.4375f);
    advance(3);
#pragma unroll
    for (int hh = 12; hh < 16; hh++) doRow(hh, (float)hh * 0.125f - 1.4375f);
}

// ---------------------------------------------------------------------------
extern "C" void kernel_launch(void* const* d_in, const int* in_sizes, int n_in,
                              void* d_out, int out_size) {
    const float* psf = (const float*)d_in[0];
    const float* fm  = (const float*)d_in[1];
    const float* w1  = (const float*)d_in[2];
    const float* b1  = (const float*)d_in[3];
    const float* ws  = (const float*)d_in[4];
    const float* bs  = (const float*)d_in[5];
    float* out = (float*)d_out;

    // kA: plain launch
    kA<<<1024, 256>>>(psf);

    // kB, kC: programmatic dependent launches (PDL)
    cudaLaunchAttribute attr[1];
    attr[0].id = cudaLaunchAttributeProgrammaticStreamSerialization;
    attr[0].val.programmaticStreamSerializationAllowed = 1;

    {
        cudaLaunchConfig_t cfg = {};
        cfg.gridDim  = dim3(9, 4, NB);
        cfg.blockDim = dim3(256, 1, 1);
        cfg.attrs = attr;
        cfg.numAttrs = 1;
        cudaLaunchKernelEx(&cfg, kB, w1, b1, ws, bs);
    }
    {
        cudaLaunchConfig_t cfg = {};
        cfg.gridDim  = dim3(16, C_CH, NB);
        cfg.blockDim = dim3(128, 1, 1);
        cfg.attrs = attr;
        cfg.numAttrs = 1;
        cudaLaunchKernelEx(&cfg, kC, fm, out);
    }
}

// round 15
// speedup vs baseline: 1.1745x; 1.0701x over previous
#include <cuda_runtime.h>

#define C_CH 32
#define HW   256
#define KS2  9
#define OCH  288
#define QS   32
#define NB   4

#define FSTR 264   // fmt row stride (words); interior cols 4..259 (16B aligned)

__device__ float g_p[NB * C_CH * QS * QS];   // [n][c][32][32]
__device__ float g_y[NB * OCH * QS * QS];    // [n][o][32][32]

// ---- f32x2 packed helpers (sm_103a native) ----
typedef unsigned long long u64;
__device__ __forceinline__ u64 pk2(float lo, float hi) {
    u64 r; asm("mov.b64 %0, {%1, %2};" : "=l"(r) : "f"(lo), "f"(hi)); return r;
}
__device__ __forceinline__ float2 unpk2(u64 v) {
    float2 f; asm("mov.b64 {%0, %1}, %2;" : "=f"(f.x), "=f"(f.y) : "l"(v)); return f;
}
__device__ __forceinline__ u64 ffma2(u64 a, u64 b, u64 c) {
    u64 d; asm("fma.rn.f32x2 %0, %1, %2, %3;" : "=l"(d) : "l"(a), "l"(b), "l"(c)); return d;
}
__device__ __forceinline__ u64 fadd2(u64 a, u64 b) {
    u64 d; asm("add.rn.f32x2 %0, %1, %2;" : "=l"(d) : "l"(a), "l"(b)); return d;
}
__device__ __forceinline__ u64 fneg2(u64 a) { return a ^ 0x8000000080000000ULL; }

// ---------------------------------------------------------------------------
// Kernel A: psf -> bilinear 1/4 -> maxpool2 -> g_p.
// Triggers PDL at the TOP: kB may launch immediately; its gridDepSync still
// waits for kA's completion before touching g_p.
// ---------------------------------------------------------------------------
__global__ void __launch_bounds__(256) kA(const float* __restrict__ psf) {
    cudaTriggerProgrammaticLaunchCompletion();

    const int b  = blockIdx.x;
    const int it = b & 7;
    const int c  = (b >> 3) & 31;
    const int n  = b >> 8;
    const int tid  = threadIdx.x;
    const int warp = tid >> 5;
    const int lane = tid & 31;
    const int ii   = warp >> 1;
    const int half = warp & 1;
    const int i = it * 4 + ii;

    const float4* base = (const float4*)(psf + ((size_t)(n * C_CH + c) * HW) * HW);
    const int r0 = 8 * i + 1 + 4 * half;
    const float4* p0 = base + r0 * (HW / 4);
    const float4* p1 = p0 + (HW / 4);

    float4 a0 = __ldg(p0 + lane);
    float4 a1 = __ldg(p0 + 32 + lane);
    float4 b0 = __ldg(p1 + lane);
    float4 b1 = __ldg(p1 + 32 + lane);

    float slo = (a0.y + a0.z) + (b0.y + b0.z);
    float shi = (a1.y + a1.z) + (b1.y + b1.z);
    slo = fmaxf(slo, __shfl_xor_sync(0xffffffffu, slo, 1));
    shi = fmaxf(shi, __shfl_xor_sync(0xffffffffu, shi, 1));

    __shared__ float sm[2][4][32];
    if ((lane & 1) == 0) {
        int j = lane >> 1;
        sm[half][ii][j]      = slo;
        sm[half][ii][j + 16] = shi;
    }
    __syncthreads();

    if (tid < 128) {
        int j  = tid & 31;
        int iw = tid >> 5;
        float m = fmaxf(sm[0][iw][j], sm[1][iw][j]);
        g_p[((size_t)(n * C_CH + c) * QS + it * 4 + iw) * QS + j] = 0.25f * m;
    }
}

// ---------------------------------------------------------------------------
// Kernel B: smem-tiled f32x2 matmul. Triggers PDL at the TOP so kC's fmt
// staging (the big fm-read phase) overlaps all of kB and kA's tail.
// ---------------------------------------------------------------------------
__global__ void __launch_bounds__(256) kB(const float* __restrict__ w1,
                                          const float* __restrict__ b1,
                                          const float* __restrict__ bs_w,
                                          const float* __restrict__ bs_b) {
    cudaTriggerProgrammaticLaunchCompletion();

    __shared__ float p_sm[C_CH][256];
    __shared__ float w_sm1[32][32];
    __shared__ float w_sms[32][32];

    const int og    = blockIdx.x;
    const int ptile = blockIdx.y;
    const int n     = blockIdx.z;
    const int t     = threadIdx.x;
    const int lane  = t & 31;
    const int osub  = t >> 5;

    // ---- independent prologue: weight slice staging ----
    {
        int ol = t >> 3;
        int cq = t & 7;
        *(float4*)&w_sm1[ol][4 * cq] = __ldg((const float4*)(w1 + (og * 32 + ol) * C_CH) + cq);
        *(float4*)&w_sms[ol][4 * cq] = __ldg((const float4*)(bs_w + (og * 32 + ol) * C_CH) + cq);
    }

    // ---- wait for kA's g_p ----
    cudaGridDependencySynchronize();

    const float4* pg = (const float4*)(g_p + (size_t)n * (C_CH * QS * QS) + ptile * 256);
#pragma unroll
    for (int v = 0; v < 8; v++) {
        int idx = v * 256 + t;
        int c  = idx >> 6;
        int f4 = idx & 63;
        *(float4*)&p_sm[c][4 * f4] = __ldg(pg + c * (1024 / 4) + f4);
    }
    __syncthreads();

    u64 acc1[4][4], acc2[4][4];
#pragma unroll
    for (int m = 0; m < 4; m++)
#pragma unroll
        for (int i = 0; i < 4; i++) { acc1[m][i] = 0; acc2[m][i] = 0; }

#pragma unroll
    for (int c = 0; c < C_CH; c++) {
        u64 p2[4];
#pragma unroll
        for (int i = 0; i < 4; i++)
            p2[i] = *(const u64*)&p_sm[c][2 * (lane + 32 * i)];
#pragma unroll
        for (int m = 0; m < 4; m++) {
            int ol = osub * 4 + m;
            float w1c = w_sm1[ol][c];
            float wsc = w_sms[ol][c];
            u64 w12 = pk2(w1c, w1c);
            u64 ws2 = pk2(wsc, wsc);
#pragma unroll
            for (int i = 0; i < 4; i++) {
                acc1[m][i] = ffma2(w12, p2[i], acc1[m][i]);
                acc2[m][i] = ffma2(ws2, p2[i], acc2[m][i]);
            }
        }
    }

    float* yb = g_y + (size_t)n * (OCH * QS * QS) + (size_t)og * 32 * 1024 + ptile * 256;
#pragma unroll
    for (int m = 0; m < 4; m++) {
        int ol = osub * 4 + m;
        int o  = og * 32 + ol;
        float bb1 = __ldg(b1 + o);
        float bbs = __ldg(bs_b + o);
#pragma unroll
        for (int i = 0; i < 4; i++) {
            float2 d1 = unpk2(acc1[m][i]);
            float2 d2 = unpk2(acc2[m][i]);
            float z0 = d1.x + bb1, z1 = d1.y + bb1;
            float a0 = (z0 >= 0.f) ? z0 : 0.2f * z0;
            float a1 = (z1 >= 0.f) ? z1 : 0.2f * z1;
            float2 r = make_float2(a0 + d2.x + bbs, a1 + d2.y + bbs);
            *(float2*)&yb[ol * 1024 + 2 * (lane + 32 * i)] = r;
        }
    }
}

// ---------------------------------------------------------------------------
// Kernel C: f32x2 column-pair FAC. PDL: fmt staging (independent of kB),
// gridDepSync, then yt from g_y. Math unchanged (R11).
// ---------------------------------------------------------------------------
__global__ void __launch_bounds__(128) kC(const float* __restrict__ fm,
                                          float* __restrict__ out) {
    __shared__ float fmt[18 * FSTR];
    __shared__ __align__(16) float yt[4][32][12];

    const int tt = blockIdx.x;
    const int c  = blockIdx.y;
    const int n  = blockIdx.z;
    const int j  = threadIdx.x;          // 0..127, columns (2j, 2j+1)
    const int h0 = tt * 16;
    const int crBase = 2 * tt - 1;

    // ---- independent prologue: featuremap tile staging ----
    const float4* fbase4 = (const float4*)(fm + ((size_t)(n * C_CH + c) * HW) * HW);
    const float4 z4 = make_float4(0.f, 0.f, 0.f, 0.f);
#pragma unroll
    for (int v = 0; v < 9; v++) {
        int idx = v * 128 + j;
        int r = idx >> 6;
        int q = idx & 63;
        int gh = h0 - 1 + r;
        float4 val = (gh >= 0 && gh < HW) ? __ldg(fbase4 + gh * (HW / 4) + q) : z4;
        *(float4*)&fmt[r * FSTR + 4 + 4 * q] = val;
    }
    if (j < 36) {
        int r = j >> 1;
        fmt[r * FSTR + 3 + 257 * (j & 1)] = 0.f;
    }

    // ---- wait for kB's g_y ----
    cudaGridDependencySynchronize();

    const float* ybase = g_y + (size_t)(n * OCH + c * KS2) * (QS * QS);
#pragma unroll
    for (int v = 0; v < 3; v++) {
        int idx = v * 128 + j;
        if (idx < 288) {
            int q  = idx & 7;
            int rk = idx >> 3;
            int r  = rk / KS2;
            int k  = rk - r * KS2;
            int cr = min(max(crBase + r, 0), QS - 1);
            float4 s = __ldg((const float4*)(ybase + k * (QS * QS) + cr * QS) + q);
            int col = 4 * q;
            yt[r][col + 0][k] = s.x;
            yt[r][col + 1][k] = s.y;
            yt[r][col + 2][k] = s.z;
            yt[r][col + 3][k] = s.w;
        }
    }
    __syncthreads();

    const int c0 = 2 * j;
    int ix0 = (c0 - 4) >> 3;
    float wx0 = (float)c0 * 0.125f - 0.4375f - (float)ix0;
    float wx1 = wx0 + 0.125f;
    const int jx0 = max(ix0, 0);
    const int jx1 = min(ix0 + 1, QS - 1);

    u64 hl2[KS2], df2[KS2];
    auto loadHL2 = [&](int r, u64* dst) {
        const float4* pa = (const float4*)yt[r][jx0];
        const float4* pb = (const float4*)yt[r][jx1];
        float4 a0 = pa[0], a1 = pa[1];
        float4 b0 = pb[0], b1 = pb[1];
        float  a8 = yt[r][jx0][8];
        float  b8 = yt[r][jx1][8];
        float ta[KS2];
        ta[0] = b0.x - a0.x; ta[1] = b0.y - a0.y; ta[2] = b0.z - a0.z;
        ta[3] = b0.w - a0.w; ta[4] = b1.x - a1.x; ta[5] = b1.y - a1.y;
        ta[6] = b1.z - a1.z; ta[7] = b1.w - a1.w; ta[8] = b8 - a8;
        float av[KS2];
        av[0] = a0.x; av[1] = a0.y; av[2] = a0.z; av[3] = a0.w;
        av[4] = a1.x; av[5] = a1.y; av[6] = a1.z; av[7] = a1.w; av[8] = a8;
#pragma unroll
        for (int k = 0; k < KS2; k++)
            dst[k] = pk2(fmaf(wx0, ta[k], av[k]), fmaf(wx1, ta[k], av[k]));
    };

    loadHL2(0, hl2);
    loadHL2(1, df2);
#pragma unroll
    for (int k = 0; k < KS2; k++) df2[k] = fadd2(df2[k], fneg2(hl2[k]));

    auto advance = [&](int newRow) {
#pragma unroll
        for (int k = 0; k < KS2; k++) hl2[k] = fadd2(hl2[k], df2[k]);
        loadHL2(newRow, df2);
#pragma unroll
        for (int k = 0; k < KS2; k++) df2[k] = fadd2(df2[k], fneg2(hl2[k]));
    };

    const float* fcol = fmt + 3 + c0;
    u64 P[3][3];
#pragma unroll
    for (int r = 0; r < 2; r++) {
        float f0 = fcol[r * FSTR + 0], f1 = fcol[r * FSTR + 1];
        float f2 = fcol[r * FSTR + 2], f3 = fcol[r * FSTR + 3];
        P[r][0] = pk2(f0, f1); P[r][1] = pk2(f1, f2); P[r][2] = pk2(f2, f3);
    }

    float2* ob = (float2*)(out + (((size_t)(n * C_CH + c) * HW + h0) * HW) + c0);

    auto doRow = [&](int hh, float wy) {
        {
            float f0 = fcol[(hh + 2) * FSTR + 0], f1 = fcol[(hh + 2) * FSTR + 1];
            float f2 = fcol[(hh + 2) * FSTR + 2], f3 = fcol[(hh + 2) * FSTR + 3];
            P[2][0] = pk2(f0, f1); P[2][1] = pk2(f1, f2); P[2][2] = pk2(f2, f3);
        }
        u64 wy2 = pk2(wy, wy);
        u64 accA = 0, accB = 0;
#pragma unroll
        for (int dy = 0; dy < 3; dy++) {
#pragma unroll
            for (int dx = 0; dx < 3; dx++) {
                int k = dy * 3 + dx;
                u64 ft = ffma2(wy2, df2[k], hl2[k]);
                if (k < 5) accA = ffma2(ft, P[dy][dx], accA);
                else       accB = ffma2(ft, P[dy][dx], accB);
            }
        }
        ob[hh * (HW / 2)] = unpk2(fadd2(accA, accB));
#pragma unroll
        for (int d = 0; d < 3; d++) { P[0][d] = P[1][d]; P[1][d] = P[2][d]; }
    };

#pragma unroll
    for (int hh = 0; hh < 4; hh++)   doRow(hh, (float)hh * 0.125f + 0.5625f);
    advance(2);
#pragma unroll
    for (int hh = 4; hh < 12; hh++)  doRow(hh, (float)hh * 0.125f - 0.4375f);
    advance(3);
#pragma unroll
    for (int hh = 12; hh < 16; hh++) doRow(hh, (float)hh * 0.125f - 1.4375f);
}

// ---------------------------------------------------------------------------
extern "C" void kernel_launch(void* const* d_in, const int* in_sizes, int n_in,
                              void* d_out, int out_size) {
    const float* psf = (const float*)d_in[0];
    const float* fm  = (const float*)d_in[1];
    const float* w1  = (const float*)d_in[2];
    const float* b1  = (const float*)d_in[3];
    const float* ws  = (const float*)d_in[4];
    const float* bs  = (const float*)d_in[5];
    float* out = (float*)d_out;

    // kA: plain launch
    kA<<<1024, 256>>>(psf);

    // kB, kC: programmatic dependent launches (PDL)
    cudaLaunchAttribute attr[1];
    attr[0].id = cudaLaunchAttributeProgrammaticStreamSerialization;
    attr[0].val.programmaticStreamSerializationAllowed = 1;

    {
        cudaLaunchConfig_t cfg = {};
        cfg.gridDim  = dim3(9, 4, NB);
        cfg.blockDim = dim3(256, 1, 1);
        cfg.attrs = attr;
        cfg.numAttrs = 1;
        cudaLaunchKernelEx(&cfg, kB, w1, b1, ws, bs);
    }
    {
        cudaLaunchConfig_t cfg = {};
        cfg.gridDim  = dim3(16, C_CH, NB);
        cfg.blockDim = dim3(128, 1, 1);
        cfg.attrs = attr;
        cfg.numAttrs = 1;
        cudaLaunchKernelEx(&cfg, kC, fm, out);
    }
}

// round 16
// speedup vs baseline: 1.1777x; 1.0028x over previous
#include <cuda_runtime.h>

#define C_CH 32
#define HW   256
#define KS2  9
#define OCH  288
#define QS   32
#define NB   4

#define FSTR 264   // fmt row stride (words); interior cols 4..259 (16B aligned)

__device__ float g_p[NB * C_CH * QS * QS];   // [n][c][32][32]
__device__ float g_y[NB * OCH * QS * QS];    // [n][o][32][32]

// ---- f32x2 packed helpers (sm_103a native) ----
typedef unsigned long long u64;
__device__ __forceinline__ u64 pk2(float lo, float hi) {
    u64 r; asm("mov.b64 %0, {%1, %2};" : "=l"(r) : "f"(lo), "f"(hi)); return r;
}
__device__ __forceinline__ float2 unpk2(u64 v) {
    float2 f; asm("mov.b64 {%0, %1}, %2;" : "=f"(f.x), "=f"(f.y) : "l"(v)); return f;
}
__device__ __forceinline__ u64 ffma2(u64 a, u64 b, u64 c) {
    u64 d; asm("fma.rn.f32x2 %0, %1, %2, %3;" : "=l"(d) : "l"(a), "l"(b), "l"(c)); return d;
}
__device__ __forceinline__ u64 fadd2(u64 a, u64 b) {
    u64 d; asm("add.rn.f32x2 %0, %1, %2;" : "=l"(d) : "l"(a), "l"(b)); return d;
}
__device__ __forceinline__ u64 fneg2(u64 a) { return a ^ 0x8000000080000000ULL; }

// ---------------------------------------------------------------------------
// Kernel A: psf -> bilinear 1/4 -> maxpool2 -> g_p. PDL trigger at top.
// ---------------------------------------------------------------------------
__global__ void __launch_bounds__(256) kA(const float* __restrict__ psf) {
    cudaTriggerProgrammaticLaunchCompletion();

    const int b  = blockIdx.x;
    const int it = b & 7;
    const int c  = (b >> 3) & 31;
    const int n  = b >> 8;
    const int tid  = threadIdx.x;
    const int warp = tid >> 5;
    const int lane = tid & 31;
    const int ii   = warp >> 1;
    const int half = warp & 1;
    const int i = it * 4 + ii;

    const float4* base = (const float4*)(psf + ((size_t)(n * C_CH + c) * HW) * HW);
    const int r0 = 8 * i + 1 + 4 * half;
    const float4* p0 = base + r0 * (HW / 4);
    const float4* p1 = p0 + (HW / 4);

    float4 a0 = __ldg(p0 + lane);
    float4 a1 = __ldg(p0 + 32 + lane);
    float4 b0 = __ldg(p1 + lane);
    float4 b1 = __ldg(p1 + 32 + lane);

    float slo = (a0.y + a0.z) + (b0.y + b0.z);
    float shi = (a1.y + a1.z) + (b1.y + b1.z);
    slo = fmaxf(slo, __shfl_xor_sync(0xffffffffu, slo, 1));
    shi = fmaxf(shi, __shfl_xor_sync(0xffffffffu, shi, 1));

    __shared__ float sm[2][4][32];
    if ((lane & 1) == 0) {
        int j = lane >> 1;
        sm[half][ii][j]      = slo;
        sm[half][ii][j + 16] = shi;
    }
    __syncthreads();

    if (tid < 128) {
        int j  = tid & 31;
        int iw = tid >> 5;
        float m = fmaxf(sm[0][iw][j], sm[1][iw][j]);
        g_p[((size_t)(n * C_CH + c) * QS + it * 4 + iw) * QS + j] = 0.25f * m;
    }
}

// ---------------------------------------------------------------------------
// Kernel B: smem-tiled f32x2 matmul. PDL trigger at top.
// ---------------------------------------------------------------------------
__global__ void __launch_bounds__(256) kB(const float* __restrict__ w1,
                                          const float* __restrict__ b1,
                                          const float* __restrict__ bs_w,
                                          const float* __restrict__ bs_b) {
    cudaTriggerProgrammaticLaunchCompletion();

    __shared__ float p_sm[C_CH][256];
    __shared__ float w_sm1[32][32];
    __shared__ float w_sms[32][32];

    const int og    = blockIdx.x;
    const int ptile = blockIdx.y;
    const int n     = blockIdx.z;
    const int t     = threadIdx.x;
    const int lane  = t & 31;
    const int osub  = t >> 5;

    {
        int ol = t >> 3;
        int cq = t & 7;
        *(float4*)&w_sm1[ol][4 * cq] = __ldg((const float4*)(w1 + (og * 32 + ol) * C_CH) + cq);
        *(float4*)&w_sms[ol][4 * cq] = __ldg((const float4*)(bs_w + (og * 32 + ol) * C_CH) + cq);
    }

    cudaGridDependencySynchronize();

    const float4* pg = (const float4*)(g_p + (size_t)n * (C_CH * QS * QS) + ptile * 256);
#pragma unroll
    for (int v = 0; v < 8; v++) {
        int idx = v * 256 + t;
        int c  = idx >> 6;
        int f4 = idx & 63;
        *(float4*)&p_sm[c][4 * f4] = __ldg(pg + c * (1024 / 4) + f4);
    }
    __syncthreads();

    u64 acc1[4][4], acc2[4][4];
#pragma unroll
    for (int m = 0; m < 4; m++)
#pragma unroll
        for (int i = 0; i < 4; i++) { acc1[m][i] = 0; acc2[m][i] = 0; }

#pragma unroll
    for (int c = 0; c < C_CH; c++) {
        u64 p2[4];
#pragma unroll
        for (int i = 0; i < 4; i++)
            p2[i] = *(const u64*)&p_sm[c][2 * (lane + 32 * i)];
#pragma unroll
        for (int m = 0; m < 4; m++) {
            int ol = osub * 4 + m;
            float w1c = w_sm1[ol][c];
            float wsc = w_sms[ol][c];
            u64 w12 = pk2(w1c, w1c);
            u64 ws2 = pk2(wsc, wsc);
#pragma unroll
            for (int i = 0; i < 4; i++) {
                acc1[m][i] = ffma2(w12, p2[i], acc1[m][i]);
                acc2[m][i] = ffma2(ws2, p2[i], acc2[m][i]);
            }
        }
    }

    float* yb = g_y + (size_t)n * (OCH * QS * QS) + (size_t)og * 32 * 1024 + ptile * 256;
#pragma unroll
    for (int m = 0; m < 4; m++) {
        int ol = osub * 4 + m;
        int o  = og * 32 + ol;
        float bb1 = __ldg(b1 + o);
        float bbs = __ldg(bs_b + o);
#pragma unroll
        for (int i = 0; i < 4; i++) {
            float2 d1 = unpk2(acc1[m][i]);
            float2 d2 = unpk2(acc2[m][i]);
            float z0 = d1.x + bb1, z1 = d1.y + bb1;
            float a0 = (z0 >= 0.f) ? z0 : 0.2f * z0;
            float a1 = (z1 >= 0.f) ? z1 : 0.2f * z1;
            float2 r = make_float2(a0 + d2.x + bbs, a1 + d2.y + bbs);
            *(float2*)&yb[ol * 1024 + 2 * (lane + 32 * i)] = r;
        }
    }
}

// ---------------------------------------------------------------------------
// Kernel C: f32x2 column-pair FAC. Output stores use __stcs (evict-first)
// so `out` never pollutes L2 -> psf+fm stay L2-resident across replays.
// ---------------------------------------------------------------------------
__global__ void __launch_bounds__(128) kC(const float* __restrict__ fm,
                                          float* __restrict__ out) {
    __shared__ float fmt[18 * FSTR];
    __shared__ __align__(16) float yt[4][32][12];

    const int tt = blockIdx.x;
    const int c  = blockIdx.y;
    const int n  = blockIdx.z;
    const int j  = threadIdx.x;          // 0..127, columns (2j, 2j+1)
    const int h0 = tt * 16;
    const int crBase = 2 * tt - 1;

    // ---- independent prologue: featuremap tile staging ----
    const float4* fbase4 = (const float4*)(fm + ((size_t)(n * C_CH + c) * HW) * HW);
    const float4 z4 = make_float4(0.f, 0.f, 0.f, 0.f);
#pragma unroll
    for (int v = 0; v < 9; v++) {
        int idx = v * 128 + j;
        int r = idx >> 6;
        int q = idx & 63;
        int gh = h0 - 1 + r;
        float4 val = (gh >= 0 && gh < HW) ? __ldg(fbase4 + gh * (HW / 4) + q) : z4;
        *(float4*)&fmt[r * FSTR + 4 + 4 * q] = val;
    }
    if (j < 36) {
        int r = j >> 1;
        fmt[r * FSTR + 3 + 257 * (j & 1)] = 0.f;
    }

    // ---- wait for kB's g_y ----
    cudaGridDependencySynchronize();

    const float* ybase = g_y + (size_t)(n * OCH + c * KS2) * (QS * QS);
#pragma unroll
    for (int v = 0; v < 3; v++) {
        int idx = v * 128 + j;
        if (idx < 288) {
            int q  = idx & 7;
            int rk = idx >> 3;
            int r  = rk / KS2;
            int k  = rk - r * KS2;
            int cr = min(max(crBase + r, 0), QS - 1);
            float4 s = __ldg((const float4*)(ybase + k * (QS * QS) + cr * QS) + q);
            int col = 4 * q;
            yt[r][col + 0][k] = s.x;
            yt[r][col + 1][k] = s.y;
            yt[r][col + 2][k] = s.z;
            yt[r][col + 3][k] = s.w;
        }
    }
    __syncthreads();

    const int c0 = 2 * j;
    int ix0 = (c0 - 4) >> 3;
    float wx0 = (float)c0 * 0.125f - 0.4375f - (float)ix0;
    float wx1 = wx0 + 0.125f;
    const int jx0 = max(ix0, 0);
    const int jx1 = min(ix0 + 1, QS - 1);

    u64 hl2[KS2], df2[KS2];
    auto loadHL2 = [&](int r, u64* dst) {
        const float4* pa = (const float4*)yt[r][jx0];
        const float4* pb = (const float4*)yt[r][jx1];
        float4 a0 = pa[0], a1 = pa[1];
        float4 b0 = pb[0], b1 = pb[1];
        float  a8 = yt[r][jx0][8];
        float  b8 = yt[r][jx1][8];
        float ta[KS2];
        ta[0] = b0.x - a0.x; ta[1] = b0.y - a0.y; ta[2] = b0.z - a0.z;
        ta[3] = b0.w - a0.w; ta[4] = b1.x - a1.x; ta[5] = b1.y - a1.y;
        ta[6] = b1.z - a1.z; ta[7] = b1.w - a1.w; ta[8] = b8 - a8;
        float av[KS2];
        av[0] = a0.x; av[1] = a0.y; av[2] = a0.z; av[3] = a0.w;
        av[4] = a1.x; av[5] = a1.y; av[6] = a1.z; av[7] = a1.w; av[8] = a8;
#pragma unroll
        for (int k = 0; k < KS2; k++)
            dst[k] = pk2(fmaf(wx0, ta[k], av[k]), fmaf(wx1, ta[k], av[k]));
    };

    loadHL2(0, hl2);
    loadHL2(1, df2);
#pragma unroll
    for (int k = 0; k < KS2; k++) df2[k] = fadd2(df2[k], fneg2(hl2[k]));

    auto advance = [&](int newRow) {
#pragma unroll
        for (int k = 0; k < KS2; k++) hl2[k] = fadd2(hl2[k], df2[k]);
        loadHL2(newRow, df2);
#pragma unroll
        for (int k = 0; k < KS2; k++) df2[k] = fadd2(df2[k], fneg2(hl2[k]));
    };

    const float* fcol = fmt + 3 + c0;
    u64 P[3][3];
#pragma unroll
    for (int r = 0; r < 2; r++) {
        float f0 = fcol[r * FSTR + 0], f1 = fcol[r * FSTR + 1];
        float f2 = fcol[r * FSTR + 2], f3 = fcol[r * FSTR + 3];
        P[r][0] = pk2(f0, f1); P[r][1] = pk2(f1, f2); P[r][2] = pk2(f2, f3);
    }

    float2* ob = (float2*)(out + (((size_t)(n * C_CH + c) * HW + h0) * HW) + c0);

    auto doRow = [&](int hh, float wy) {
        {
            float f0 = fcol[(hh + 2) * FSTR + 0], f1 = fcol[(hh + 2) * FSTR + 1];
            float f2 = fcol[(hh + 2) * FSTR + 2], f3 = fcol[(hh + 2) * FSTR + 3];
            P[2][0] = pk2(f0, f1); P[2][1] = pk2(f1, f2); P[2][2] = pk2(f2, f3);
        }
        u64 wy2 = pk2(wy, wy);
        u64 accA = 0, accB = 0;
#pragma unroll
        for (int dy = 0; dy < 3; dy++) {
#pragma unroll
            for (int dx = 0; dx < 3; dx++) {
                int k = dy * 3 + dx;
                u64 ft = ffma2(wy2, df2[k], hl2[k]);
                if (k < 5) accA = ffma2(ft, P[dy][dx], accA);
                else       accB = ffma2(ft, P[dy][dx], accB);
            }
        }
        __stcs(ob + hh * (HW / 2), unpk2(fadd2(accA, accB)));   // streaming store
#pragma unroll
        for (int d = 0; d < 3; d++) { P[0][d] = P[1][d]; P[1][d] = P[2][d]; }
    };

#pragma unroll
    for (int hh = 0; hh < 4; hh++)   doRow(hh, (float)hh * 0.125f + 0.5625f);
    advance(2);
#pragma unroll
    for (int hh = 4; hh < 12; hh++)  doRow(hh, (float)hh * 0.125f - 0.4375f);
    advance(3);
#pragma unroll
    for (int hh = 12; hh < 16; hh++) doRow(hh, (float)hh * 0.125f - 1.4375f);
}

// ---------------------------------------------------------------------------
extern "C" void kernel_launch(void* const* d_in, const int* in_sizes, int n_in,
                              void* d_out, int out_size) {
    const float* psf = (const float*)d_in[0];
    const float* fm  = (const float*)d_in[1];
    const float* w1  = (const float*)d_in[2];
    const float* b1  = (const float*)d_in[3];
    const float* ws  = (const float*)d_in[4];
    const float* bs  = (const float*)d_in[5];
    float* out = (float*)d_out;

    // kA: plain launch
    kA<<<1024, 256>>>(psf);

    // kB, kC: programmatic dependent launches (PDL)
    cudaLaunchAttribute attr[1];
    attr[0].id = cudaLaunchAttributeProgrammaticStreamSerialization;
    attr[0].val.programmaticStreamSerializationAllowed = 1;

    {
        cudaLaunchConfig_t cfg = {};
        cfg.gridDim  = dim3(9, 4, NB);
        cfg.blockDim = dim3(256, 1, 1);
        cfg.attrs = attr;
        cfg.numAttrs = 1;
        cudaLaunchKernelEx(&cfg, kB, w1, b1, ws, bs);
    }
    {
        cudaLaunchConfig_t cfg = {};
        cfg.gridDim  = dim3(16, C_CH, NB);
        cfg.blockDim = dim3(128, 1, 1);
        cfg.attrs = attr;
        cfg.numAttrs = 1;
        cudaLaunchKernelEx(&cfg, kC, fm, out);
    }
}

// round 17
// speedup vs baseline: 1.1875x; 1.0083x over previous
#include <cuda_runtime.h>

#define C_CH 32
#define HW   256
#define KS2  9
#define OCH  288
#define QS   32
#define NB   4

#define FSTR 264   // fmt row stride (words); interior cols 4..259 (16B aligned)

__device__ float g_p[NB * C_CH * QS * QS];   // [n][c][32][32]
__device__ float g_y[NB * OCH * QS * QS];    // [n][o][32][32]

// ---- f32x2 packed helpers (sm_103a native) ----
typedef unsigned long long u64;
__device__ __forceinline__ u64 pk2(float lo, float hi) {
    u64 r; asm("mov.b64 %0, {%1, %2};" : "=l"(r) : "f"(lo), "f"(hi)); return r;
}
__device__ __forceinline__ float2 unpk2(u64 v) {
    float2 f; asm("mov.b64 {%0, %1}, %2;" : "=f"(f.x), "=f"(f.y) : "l"(v)); return f;
}
__device__ __forceinline__ u64 ffma2(u64 a, u64 b, u64 c) {
    u64 d; asm("fma.rn.f32x2 %0, %1, %2, %3;" : "=l"(d) : "l"(a), "l"(b), "l"(c)); return d;
}
__device__ __forceinline__ u64 fadd2(u64 a, u64 b) {
    u64 d; asm("add.rn.f32x2 %0, %1, %2;" : "=l"(d) : "l"(a), "l"(b)); return d;
}
__device__ __forceinline__ u64 fneg2(u64 a) { return a ^ 0x8000000080000000ULL; }

// ---------------------------------------------------------------------------
// Kernel A: psf -> bilinear 1/4 -> maxpool2 -> g_p. PDL trigger at top.
// ---------------------------------------------------------------------------
__global__ void __launch_bounds__(256) kA(const float* __restrict__ psf) {
    cudaTriggerProgrammaticLaunchCompletion();

    const int b  = blockIdx.x;
    const int it = b & 7;
    const int c  = (b >> 3) & 31;
    const int n  = b >> 8;
    const int tid  = threadIdx.x;
    const int warp = tid >> 5;
    const int lane = tid & 31;
    const int ii   = warp >> 1;
    const int half = warp & 1;
    const int i = it * 4 + ii;

    const float4* base = (const float4*)(psf + ((size_t)(n * C_CH + c) * HW) * HW);
    const int r0 = 8 * i + 1 + 4 * half;
    const float4* p0 = base + r0 * (HW / 4);
    const float4* p1 = p0 + (HW / 4);

    float4 a0 = __ldg(p0 + lane);
    float4 a1 = __ldg(p0 + 32 + lane);
    float4 b0 = __ldg(p1 + lane);
    float4 b1 = __ldg(p1 + 32 + lane);

    float slo = (a0.y + a0.z) + (b0.y + b0.z);
    float shi = (a1.y + a1.z) + (b1.y + b1.z);
    slo = fmaxf(slo, __shfl_xor_sync(0xffffffffu, slo, 1));
    shi = fmaxf(shi, __shfl_xor_sync(0xffffffffu, shi, 1));

    __shared__ float sm[2][4][32];
    if ((lane & 1) == 0) {
        int j = lane >> 1;
        sm[half][ii][j]      = slo;
        sm[half][ii][j + 16] = shi;
    }
    __syncthreads();

    if (tid < 128) {
        int j  = tid & 31;
        int iw = tid >> 5;
        float m = fmaxf(sm[0][iw][j], sm[1][iw][j]);
        g_p[((size_t)(n * C_CH + c) * QS + it * 4 + iw) * QS + j] = 0.25f * m;
    }
}

// ---------------------------------------------------------------------------
// Kernel B: smem-tiled f32x2 matmul. PDL trigger at top. g_p via __ldcs.
// ---------------------------------------------------------------------------
__global__ void __launch_bounds__(256) kB(const float* __restrict__ w1,
                                          const float* __restrict__ b1,
                                          const float* __restrict__ bs_w,
                                          const float* __restrict__ bs_b) {
    cudaTriggerProgrammaticLaunchCompletion();

    __shared__ float p_sm[C_CH][256];
    __shared__ float w_sm1[32][32];
    __shared__ float w_sms[32][32];

    const int og    = blockIdx.x;
    const int ptile = blockIdx.y;
    const int n     = blockIdx.z;
    const int t     = threadIdx.x;
    const int lane  = t & 31;
    const int osub  = t >> 5;

    {
        int ol = t >> 3;
        int cq = t & 7;
        *(float4*)&w_sm1[ol][4 * cq] = __ldg((const float4*)(w1 + (og * 32 + ol) * C_CH) + cq);
        *(float4*)&w_sms[ol][4 * cq] = __ldg((const float4*)(bs_w + (og * 32 + ol) * C_CH) + cq);
    }

    cudaGridDependencySynchronize();

    const float4* pg = (const float4*)(g_p + (size_t)n * (C_CH * QS * QS) + ptile * 256);
#pragma unroll
    for (int v = 0; v < 8; v++) {
        int idx = v * 256 + t;
        int c  = idx >> 6;
        int f4 = idx & 63;
        *(float4*)&p_sm[c][4 * f4] = __ldcs(pg + c * (1024 / 4) + f4);
    }
    __syncthreads();

    u64 acc1[4][4], acc2[4][4];
#pragma unroll
    for (int m = 0; m < 4; m++)
#pragma unroll
        for (int i = 0; i < 4; i++) { acc1[m][i] = 0; acc2[m][i] = 0; }

#pragma unroll
    for (int c = 0; c < C_CH; c++) {
        u64 p2[4];
#pragma unroll
        for (int i = 0; i < 4; i++)
            p2[i] = *(const u64*)&p_sm[c][2 * (lane + 32 * i)];
#pragma unroll
        for (int m = 0; m < 4; m++) {
            int ol = osub * 4 + m;
            float w1c = w_sm1[ol][c];
            float wsc = w_sms[ol][c];
            u64 w12 = pk2(w1c, w1c);
            u64 ws2 = pk2(wsc, wsc);
#pragma unroll
            for (int i = 0; i < 4; i++) {
                acc1[m][i] = ffma2(w12, p2[i], acc1[m][i]);
                acc2[m][i] = ffma2(ws2, p2[i], acc2[m][i]);
            }
        }
    }

    float* yb = g_y + (size_t)n * (OCH * QS * QS) + (size_t)og * 32 * 1024 + ptile * 256;
#pragma unroll
    for (int m = 0; m < 4; m++) {
        int ol = osub * 4 + m;
        int o  = og * 32 + ol;
        float bb1 = __ldg(b1 + o);
        float bbs = __ldg(bs_b + o);
#pragma unroll
        for (int i = 0; i < 4; i++) {
            float2 d1 = unpk2(acc1[m][i]);
            float2 d2 = unpk2(acc2[m][i]);
            float z0 = d1.x + bb1, z1 = d1.y + bb1;
            float a0 = (z0 >= 0.f) ? z0 : 0.2f * z0;
            float a1 = (z1 >= 0.f) ? z1 : 0.2f * z1;
            float2 r = make_float2(a0 + d2.x + bbs, a1 + d2.y + bbs);
            *(float2*)&yb[ol * 1024 + 2 * (lane + 32 * i)] = r;
        }
    }
}

// ---------------------------------------------------------------------------
// Kernel C: f32x2 column-pair FAC. Window via 1 LDS.64 (middle pair, aligned,
// used as P[1] directly) + 2 scalar LDS; __stcs output; __ldcs g_y reads.
// ---------------------------------------------------------------------------
__global__ void __launch_bounds__(128) kC(const float* __restrict__ fm,
                                          float* __restrict__ out) {
    __shared__ float fmt[18 * FSTR];
    __shared__ __align__(16) float yt[4][32][12];

    const int tt = blockIdx.x;
    const int c  = blockIdx.y;
    const int n  = blockIdx.z;
    const int j  = threadIdx.x;          // 0..127, columns (2j, 2j+1)
    const int h0 = tt * 16;
    const int crBase = 2 * tt - 1;

    // ---- independent prologue: featuremap tile staging ----
    const float4* fbase4 = (const float4*)(fm + ((size_t)(n * C_CH + c) * HW) * HW);
    const float4 z4 = make_float4(0.f, 0.f, 0.f, 0.f);
#pragma unroll
    for (int v = 0; v < 9; v++) {
        int idx = v * 128 + j;
        int r = idx >> 6;
        int q = idx & 63;
        int gh = h0 - 1 + r;
        float4 val = (gh >= 0 && gh < HW) ? __ldg(fbase4 + gh * (HW / 4) + q) : z4;
        *(float4*)&fmt[r * FSTR + 4 + 4 * q] = val;
    }
    if (j < 36) {
        int r = j >> 1;
        fmt[r * FSTR + 3 + 257 * (j & 1)] = 0.f;
    }

    // ---- wait for kB's g_y ----
    cudaGridDependencySynchronize();

    const float* ybase = g_y + (size_t)(n * OCH + c * KS2) * (QS * QS);
#pragma unroll
    for (int v = 0; v < 3; v++) {
        int idx = v * 128 + j;
        if (idx < 288) {
            int q  = idx & 7;
            int rk = idx >> 3;
            int r  = rk / KS2;
            int k  = rk - r * KS2;
            int cr = min(max(crBase + r, 0), QS - 1);
            float4 s = __ldcs((const float4*)(ybase + k * (QS * QS) + cr * QS) + q);
            int col = 4 * q;
            yt[r][col + 0][k] = s.x;
            yt[r][col + 1][k] = s.y;
            yt[r][col + 2][k] = s.z;
            yt[r][col + 3][k] = s.w;
        }
    }
    __syncthreads();

    const int c0 = 2 * j;
    int ix0 = (c0 - 4) >> 3;
    float wx0 = (float)c0 * 0.125f - 0.4375f - (float)ix0;
    float wx1 = wx0 + 0.125f;
    const int jx0 = max(ix0, 0);
    const int jx1 = min(ix0 + 1, QS - 1);

    u64 hl2[KS2], df2[KS2];
    auto loadHL2 = [&](int r, u64* dst) {
        const float4* pa = (const float4*)yt[r][jx0];
        const float4* pb = (const float4*)yt[r][jx1];
        float4 a0 = pa[0], a1 = pa[1];
        float4 b0 = pb[0], b1 = pb[1];
        float  a8 = yt[r][jx0][8];
        float  b8 = yt[r][jx1][8];
        float ta[KS2];
        ta[0] = b0.x - a0.x; ta[1] = b0.y - a0.y; ta[2] = b0.z - a0.z;
        ta[3] = b0.w - a0.w; ta[4] = b1.x - a1.x; ta[5] = b1.y - a1.y;
        ta[6] = b1.z - a1.z; ta[7] = b1.w - a1.w; ta[8] = b8 - a8;
        float av[KS2];
        av[0] = a0.x; av[1] = a0.y; av[2] = a0.z; av[3] = a0.w;
        av[4] = a1.x; av[5] = a1.y; av[6] = a1.z; av[7] = a1.w; av[8] = a8;
#pragma unroll
        for (int k = 0; k < KS2; k++)
            dst[k] = pk2(fmaf(wx0, ta[k], av[k]), fmaf(wx1, ta[k], av[k]));
    };

    loadHL2(0, hl2);
    loadHL2(1, df2);
#pragma unroll
    for (int k = 0; k < KS2; k++) df2[k] = fadd2(df2[k], fneg2(hl2[k]));

    auto advance = [&](int newRow) {
#pragma unroll
        for (int k = 0; k < KS2; k++) hl2[k] = fadd2(hl2[k], df2[k]);
        loadHL2(newRow, df2);
#pragma unroll
        for (int k = 0; k < KS2; k++) df2[k] = fadd2(df2[k], fneg2(hl2[k]));
    };

    // ---- window loads: middle pair (f[c0],f[c0+1]) is an aligned float2 and
    // IS P[1]; outer taps f[c0-1], f[c0+2] via independent scalar LDS ----
    const float*  fL = fmt + 3 + c0;               // f[c0-1] at row offset r*FSTR
    const float2* fM = (const float2*)(fmt + 4 + c0);  // (f[c0], f[c0+1]); FSTR/2 stride
    const float*  fR = fmt + 6 + c0;               // f[c0+2]

    u64 P[3][3];
    auto loadWin = [&](int r, u64* Pr) {
        float  a = fL[r * FSTR];
        float2 m = fM[r * (FSTR / 2)];
        float  b = fR[r * FSTR];
        Pr[0] = pk2(a, m.x);
        Pr[1] = pk2(m.x, m.y);   // folds to the loaded register pair
        Pr[2] = pk2(m.y, b);
    };
    loadWin(0, P[0]);
    loadWin(1, P[1]);

    float2* ob = (float2*)(out + (((size_t)(n * C_CH + c) * HW + h0) * HW) + c0);

    auto doRow = [&](int hh, float wy) {
        loadWin(hh + 2, P[2]);
        u64 wy2 = pk2(wy, wy);
        u64 accA = 0, accB = 0;
#pragma unroll
        for (int dy = 0; dy < 3; dy++) {
#pragma unroll
            for (int dx = 0; dx < 3; dx++) {
                int k = dy * 3 + dx;
                u64 ft = ffma2(wy2, df2[k], hl2[k]);
                if (k < 5) accA = ffma2(ft, P[dy][dx], accA);
                else       accB = ffma2(ft, P[dy][dx], accB);
            }
        }
        __stcs(ob + hh * (HW / 2), unpk2(fadd2(accA, accB)));
#pragma unroll
        for (int d = 0; d < 3; d++) { P[0][d] = P[1][d]; P[1][d] = P[2][d]; }
    };

#pragma unroll
    for (int hh = 0; hh < 4; hh++)   doRow(hh, (float)hh * 0.125f + 0.5625f);
    advance(2);
#pragma unroll
    for (int hh = 4; hh < 12; hh++)  doRow(hh, (float)hh * 0.125f - 0.4375f);
    advance(3);
#pragma unroll
    for (int hh = 12; hh < 16; hh++) doRow(hh, (float)hh * 0.125f - 1.4375f);
}

// ---------------------------------------------------------------------------
extern "C" void kernel_launch(void* const* d_in, const int* in_sizes, int n_in,
                              void* d_out, int out_size) {
    const float* psf = (const float*)d_in[0];
    const float* fm  = (const float*)d_in[1];
    const float* w1  = (const float*)d_in[2];
    const float* b1  = (const float*)d_in[3];
    const float* ws  = (const float*)d_in[4];
    const float* bs  = (const float*)d_in[5];
    float* out = (float*)d_out;

    // kA: plain launch
    kA<<<1024, 256>>>(psf);

    // kB, kC: programmatic dependent launches (PDL)
    cudaLaunchAttribute attr[1];
    attr[0].id = cudaLaunchAttributeProgrammaticStreamSerialization;
    attr[0].val.programmaticStreamSerializationAllowed = 1;

    {
        cudaLaunchConfig_t cfg = {};
        cfg.gridDim  = dim3(9, 4, NB);
        cfg.blockDim = dim3(256, 1, 1);
        cfg.attrs = attr;
        cfg.numAttrs = 1;
        cudaLaunchKernelEx(&cfg, kB, w1, b1, ws, bs);
    }
    {
        cudaLaunchConfig_t cfg = {};
        cfg.gridDim  = dim3(16, C_CH, NB);
        cfg.blockDim = dim3(128, 1, 1);
        cfg.attrs = attr;
        cfg.numAttrs = 1;
        cudaLaunchKernelEx(&cfg, kC, fm, out);
    }
}